// round 17
// baseline (speedup 1.0000x reference)
#include <cuda_runtime.h>
#include <cuda_fp16.h>
#include <math.h>
#include <stdint.h>

// ---------------- Problem dims ----------------
#define B_  2
#define T_  2048
#define D_  1024
#define H_  16
#define HS_ 64
#define BT_ (B_*T_)      // 4096
#define BH_ (B_*H_)      // 32
#define EPS_ 1e-5f

// ---------------- Scratch (static device memory; no allocations) ----------------
__device__ __align__(16) __half g_xh [BT_*D_];            // LN out, fp16
__device__ __align__(16) __half g_fh [(size_t)BT_*4*D_];  // FFN1 out, fp16
__device__ __align__(16) __half g_qh [BT_*D_];            // [B,T,H,HS] fp16
__device__ __align__(16) __half g_kh [BT_*D_];
__device__ __align__(16) __half g_vh [BT_*D_];
__device__ __align__(16) float  g_res1[BT_*D_];

// ---------------- Helpers ----------------
__device__ __forceinline__ uint32_t pk16(float lo, float hi) {
    uint32_t d;
    asm("cvt.rn.f16x2.f32 %0, %1, %2;" : "=r"(d) : "f"(hi), "f"(lo));
    return d;
}
__device__ __forceinline__ void mma_f16(float& c0, float& c1, float& c2, float& c3,
                                        uint32_t a0, uint32_t a1, uint32_t a2, uint32_t a3,
                                        uint32_t b0, uint32_t b1)
{
    asm volatile("mma.sync.aligned.m16n8k16.row.col.f32.f16.f16.f32 "
                 "{%0,%1,%2,%3}, {%4,%5,%6,%7}, {%8,%9}, {%0,%1,%2,%3};"
                 : "+f"(c0), "+f"(c1), "+f"(c2), "+f"(c3)
                 : "r"(a0), "r"(a1), "r"(a2), "r"(a3), "r"(b0), "r"(b1));
}
__device__ __forceinline__ void cp16(void* s, const void* g) {
    uint32_t sa = (uint32_t)__cvta_generic_to_shared(s);
    asm volatile("cp.async.cg.shared.global [%0], [%1], 16;" :: "r"(sa), "l"(g));
}
__device__ __forceinline__ void cp_commit() { asm volatile("cp.async.commit_group;" ::: "memory"); }
template<int N>
__device__ __forceinline__ void cp_wait() { asm volatile("cp.async.wait_group %0;" :: "n"(N) : "memory"); }
__device__ __forceinline__ void ldsm4(uint32_t& a0, uint32_t& a1, uint32_t& a2, uint32_t& a3,
                                      uint32_t addr)
{
    asm volatile("ldmatrix.sync.aligned.m8n8.x4.shared.b16 {%0,%1,%2,%3}, [%4];"
                 : "=r"(a0), "=r"(a1), "=r"(a2), "=r"(a3) : "r"(addr));
}
__device__ __forceinline__ void ldsm4t(uint32_t& a0, uint32_t& a1, uint32_t& a2, uint32_t& a3,
                                       uint32_t addr)
{
    asm volatile("ldmatrix.sync.aligned.m8n8.x4.trans.shared.b16 {%0,%1,%2,%3}, [%4];"
                 : "=r"(a0), "=r"(a1), "=r"(a2), "=r"(a3) : "r"(addr));
}

// ---------------- LayerNorm (fp16 output) ----------------
__global__ __launch_bounds__(256) void ln_kernel(const float* __restrict__ x,
                                                 const float* __restrict__ gam,
                                                 const float* __restrict__ bet,
                                                 __half* __restrict__ y)
{
    const int row = blockIdx.x;
    const int tid = threadIdx.x;
    const float4 v = *(const float4*)(x + (size_t)row*D_ + tid*4);
    float s  = v.x + v.y + v.z + v.w;
    float s2 = v.x*v.x + v.y*v.y + v.z*v.z + v.w*v.w;
    __shared__ float shs[8], shs2[8], stat[2];
    #pragma unroll
    for (int o = 16; o; o >>= 1) {
        s  += __shfl_xor_sync(0xffffffffu, s,  o);
        s2 += __shfl_xor_sync(0xffffffffu, s2, o);
    }
    if ((tid & 31) == 0) { shs[tid >> 5] = s; shs2[tid >> 5] = s2; }
    __syncthreads();
    if (tid == 0) {
        float ts = 0.f, ts2 = 0.f;
        #pragma unroll
        for (int w = 0; w < 8; ++w) { ts += shs[w]; ts2 += shs2[w]; }
        float mean = ts * (1.0f / D_);
        float var  = ts2 * (1.0f / D_) - mean * mean;
        stat[0] = mean; stat[1] = rsqrtf(var + EPS_);
    }
    __syncthreads();
    const float mean = stat[0], rstd = stat[1];
    const float4 g4 = *(const float4*)(gam + tid*4);
    const float4 b4 = *(const float4*)(bet + tid*4);
    __half2 ha = __floats2half2_rn((v.x - mean) * rstd * g4.x + b4.x,
                                   (v.y - mean) * rstd * g4.y + b4.y);
    __half2 hb = __floats2half2_rn((v.z - mean) * rstd * g4.z + b4.z,
                                   (v.w - mean) * rstd * g4.w + b4.w);
    __half2* yp = (__half2*)(y + (size_t)row*D_ + tid*4);
    yp[0] = ha; yp[1] = hb;
}

// ---------------- fp16 GEMM: MRx128 tile, BK=32, 3-stage A / 2-stage B ----------------
// MR = 128 (QKV, FFN1) or 64 (FFN2). Per-kc fragment pipeline:
// kc0 ldsm -> staging (hides ldsm latency) -> kc0 mma -> kc1 ldsm (hides under kc0 mma) -> kc1 mma.
// MODE 0: QKV (z-select; MAPB layout, no bias) -> fp16 out
// MODE 1: FFN1 (bias + relu)                   -> fp16 out
// MODE 2: FFN2 (bias + residual)               -> fp32 out
#define ASTRH 40
#define BSTRH 136

template<int MODE, int MR>
__global__ __launch_bounds__(256) void tgemm_kernel(
    const __half* __restrict__ A,
    const float* __restrict__ B0, const float* __restrict__ B1, const float* __restrict__ B2,
    const float* __restrict__ bias, const float* __restrict__ res,
    void* __restrict__ C0, void* __restrict__ C1, void* __restrict__ C2,
    int M, int N, int K)
{
    constexpr int MT = MR / 32;             // m16 tiles per warp
    __shared__ __align__(16) __half As[3][MR][ASTRH];
    __shared__ __align__(16) __half Bsh[2][32][BSTRH];

    const float* Bm;
    void* Cv;
    if (MODE == 0) {
        Bm = (blockIdx.z == 0) ? B0 : (blockIdx.z == 1 ? B1 : B2);
        Cv = (blockIdx.z == 0) ? C0 : (blockIdx.z == 1 ? C1 : C2);
    } else {
        Bm = B0;
        Cv = C0;
    }

    const int tid  = threadIdx.x;
    const int m0 = blockIdx.y * MR, n0 = blockIdx.x * 128;
    const int warp = tid >> 5, lane = tid & 31;
    const int gid = lane >> 2, tig = lane & 3;
    const int wm = (warp >> 2) * (MR / 2);
    const int wn = (warp & 3) * 32;

    const int ldrow = (lane & 7) + ((lane >> 3) & 1) * 8;
    const int ldcol = (lane >> 4) * 8;
    const uint32_t asBase = (uint32_t)__cvta_generic_to_shared(&As[0][0][0]);
    const uint32_t bsBase = (uint32_t)__cvta_generic_to_shared(&Bsh[0][0][0]);

    // A fill: MR/64 x 16B per thread per 32-k tile
    const int lar = tid >> 2;             // 0..63
    const int lacH = (tid & 3) * 8;
    // B fill: 4 float4 per thread per tile
    const int lbk = tid >> 5;
    const int lbn = (tid & 31) * 4;

    const __half* Aread = A + (size_t)(m0 + lar) * K + lacH;

    float acc[MT][4][4];
    #pragma unroll
    for (int t = 0; t < MT; ++t)
        #pragma unroll
        for (int u = 0; u < 4; ++u)
            #pragma unroll
            for (int c = 0; c < 4; ++c) acc[t][u][c] = 0.f;

    const int ntiles = K >> 5;

#define CP_A(ST, TT) do { \
        _Pragma("unroll") \
        for (int p_ = 0; p_ < MR/64; ++p_) \
            cp16(&As[ST][lar + 64*p_][lacH], Aread + (size_t)(64*p_) * K + ((TT) << 5)); \
        cp_commit(); \
    } while (0)

#define LDG_B(DST, TT) do { \
        _Pragma("unroll") \
        for (int l_ = 0; l_ < 4; ++l_) { \
            if (MODE == 0) { \
                int c_ = n0 + lbn; \
                DST[l_] = *(const float4*)(Bm + ((size_t)(c_ >> 6) * K + ((TT) << 5) + lbk + 8*l_) * HS_ + (c_ & 63)); \
            } else { \
                DST[l_] = *(const float4*)(Bm + (size_t)(((TT) << 5) + lbk + 8*l_) * N + n0 + lbn); \
            } \
        } \
    } while (0)

#define STS_B(NB, W) do { \
        _Pragma("unroll") \
        for (int l_ = 0; l_ < 4; ++l_) \
            *(uint2*)&Bsh[NB][lbk + 8*l_][lbn] = \
                make_uint2(pk16(W[l_].x, W[l_].y), pk16(W[l_].z, W[l_].w)); \
    } while (0)

#define LOAD_FRAG(KC) do { \
        const uint32_t bAddr = bsBase + \
            ((uint32_t)((curT * 32) + (KC)*16 + ldrow) * BSTRH + wn + ldcol) * 2u; \
        ldsm4t(bfr[0], bfr[1], bfr[2], bfr[3], bAddr); \
        ldsm4t(bfr[4], bfr[5], bfr[6], bfr[7], bAddr + 32u); \
        _Pragma("unroll") \
        for (int tt = 0; tt < MT; ++tt) { \
            const uint32_t aAddr = asBase + \
                ((uint32_t)(scur * MR + wm + tt*16 + ldrow) * ASTRH + (KC)*16 + ldcol) * 2u; \
            ldsm4(afr[tt][0], afr[tt][1], afr[tt][2], afr[tt][3], aAddr); \
        } \
    } while (0)

#define MMA_FRAG() do { \
        _Pragma("unroll") \
        for (int tt = 0; tt < MT; ++tt) \
            _Pragma("unroll") \
            for (int u = 0; u < 4; ++u) \
                mma_f16(acc[tt][u][0], acc[tt][u][1], acc[tt][u][2], acc[tt][u][3], \
                        afr[tt][0], afr[tt][1], afr[tt][2], afr[tt][3], \
                        bfr[u*2], bfr[u*2 + 1]); \
    } while (0)

#define GEMM_BODY(T, SW, LW) do { \
        if ((T) + 1 < ntiles) cp_wait<1>(); else cp_wait<0>(); \
        __syncthreads(); \
        const int curT = (T) & 1; \
        uint32_t bfr[8]; \
        uint32_t afr[MT][4]; \
        LOAD_FRAG(0); \
        /* staging issues while kc0 fragments land */ \
        if ((T) + 2 < ntiles) { CP_A(swr, (T) + 2); } \
        if ((T) + 1 < ntiles) { STS_B(((T) + 1) & 1, SW); } \
        if ((T) + 2 < ntiles) { LDG_B(LW, (T) + 2); } \
        MMA_FRAG(); \
        LOAD_FRAG(1); \
        MMA_FRAG(); \
        scur = (scur == 2) ? 0 : scur + 1; \
        swr  = (swr  == 2) ? 0 : swr  + 1; \
    } while (0)

    // ---- prologue ----
    int scur = 0, swr = 2;
    float4 wA[4], wB[4];
    CP_A(0, 0);
    CP_A(1, 1);
    LDG_B(wA, 0);
    STS_B(0, wA);
    if (ntiles > 1) { LDG_B(wA, 1); }

    for (int t = 0; t < ntiles; t += 2) {
        GEMM_BODY(t,     wA, wB);
        GEMM_BODY(t + 1, wB, wA);
    }

#undef GEMM_BODY
#undef MMA_FRAG
#undef LOAD_FRAG
#undef STS_B
#undef LDG_B
#undef CP_A

    // ---- epilogue ----
    #pragma unroll
    for (int t = 0; t < MT; ++t) {
        #pragma unroll
        for (int u = 0; u < 4; ++u) {
            const int m = m0 + wm + t*16 + gid;
            const int n = n0 + wn + u*8 + tig*2;
            float v0 = acc[t][u][0], v1 = acc[t][u][1];
            float v2 = acc[t][u][2], v3 = acc[t][u][3];
            if (MODE >= 1) {
                float b0 = bias[n], b1 = bias[n+1];
                v0 += b0; v1 += b1; v2 += b0; v3 += b1;
            }
            if (MODE == 1) {
                v0 = fmaxf(v0, 0.f); v1 = fmaxf(v1, 0.f);
                v2 = fmaxf(v2, 0.f); v3 = fmaxf(v3, 0.f);
            }
            if (MODE <= 1) {
                __half* Ch = (__half*)Cv;
                *(__half2*)(Ch + (size_t)m * N + n)     = __floats2half2_rn(v0, v1);
                *(__half2*)(Ch + (size_t)(m+8) * N + n) = __floats2half2_rn(v2, v3);
            } else {
                float* Cf = (float*)Cv;
                const float2 r0 = *(const float2*)(res + (size_t)m * N + n);
                const float2 r1 = *(const float2*)(res + (size_t)(m+8) * N + n);
                *(float2*)(Cf + (size_t)m * N + n)     = make_float2(v0 + r0.x, v1 + r0.y);
                *(float2*)(Cf + (size_t)(m+8) * N + n) = make_float2(v2 + r1.x, v3 + r1.y);
            }
        }
    }
}

// ---------------- Flash attention (fp16 mma, double-buffered K/V) ----------------
__global__ __launch_bounds__(128) void flash_kernel(const float* __restrict__ embds,
                                                    float* __restrict__ out)
{
    __shared__ __align__(16) __half Qh[64][72];
    __shared__ __align__(16) __half Kh[2][32][72];
    __shared__ __align__(16) __half Vh[2][32][72];
    __shared__ __align__(16) __half Ph[64][40];

    const int it = gridDim.x - 1 - blockIdx.x;   // heavy tiles first
    const int bh = blockIdx.y;
    const int b = bh >> 4, h = bh & 15;
    const int tid = threadIdx.x, warp = tid >> 5, lane = tid & 31;
    const int gid = lane >> 2, tig = lane & 3;
    const int i0 = it * 64;
    const int wr = i0 + warp * 16;

    const int ldrow = (lane & 7) + ((lane >> 3) & 1) * 8;
    const int ldcol = (lane >> 4) * 8;
    const uint32_t qBase = (uint32_t)__cvta_generic_to_shared(&Qh[0][0]);
    const uint32_t kBase = (uint32_t)__cvta_generic_to_shared(&Kh[0][0][0]);
    const uint32_t vBase = (uint32_t)__cvta_generic_to_shared(&Vh[0][0][0]);
    const uint32_t pBase = (uint32_t)__cvta_generic_to_shared(&Ph[0][0]);

    const int kvr = tid >> 3;
    const int kvc = (tid & 7) * 8;

    #pragma unroll
    for (int l = 0; l < 4; ++l) {
        int idx = l * 128 + tid;
        int r = idx >> 3, c8 = (idx & 7) * 8;
        cp16(&Qh[r][c8], g_qh + (((size_t)(b*T_ + i0 + r))*H_ + h)*HS_ + c8);
    }
    cp_commit();

#define LOAD_KV(JC, BUF) do { \
        const size_t rowb = (size_t)(b*T_ + (JC)*32); \
        cp16(&Kh[BUF][kvr     ][kvc], g_kh + ((rowb + kvr     )*H_ + h)*HS_ + kvc); \
        cp16(&Kh[BUF][kvr + 16][kvc], g_kh + ((rowb + kvr + 16)*H_ + h)*HS_ + kvc); \
        cp16(&Vh[BUF][kvr     ][kvc], g_vh + ((rowb + kvr     )*H_ + h)*HS_ + kvc); \
        cp16(&Vh[BUF][kvr + 16][kvc], g_vh + ((rowb + kvr + 16)*H_ + h)*HS_ + kvc); \
        cp_commit(); \
    } while (0)

    float oacc[8][4];
    #pragma unroll
    for (int u = 0; u < 8; ++u)
        #pragma unroll
        for (int c = 0; c < 4; ++c) oacc[u][c] = 0.f;
    float mrow[2] = {-1e30f, -1e30f};
    float lrow[2] = {0.f, 0.f};

    const int njc = 2*it + 2;
    LOAD_KV(0, 0);

    for (int jc = 0; jc < njc; ++jc) {
        const int j0 = jc * 32;
        const int buf = jc & 1;
        if (jc + 1 < njc) { LOAD_KV(jc + 1, buf ^ 1); cp_wait<1>(); }
        else              { cp_wait<0>(); }
        __syncthreads();

        if (j0 <= wr + 15) {
            float sacc[4][4];
            #pragma unroll
            for (int u = 0; u < 4; ++u)
                #pragma unroll
                for (int c = 0; c < 4; ++c) sacc[u][c] = 0.f;
            #pragma unroll
            for (int kc = 0; kc < 4; ++kc) {
                uint32_t a0, a1, a2, a3;
                ldsm4(a0, a1, a2, a3,
                      qBase + ((uint32_t)(warp*16 + ldrow) * 72 + kc*16 + ldcol) * 2u);
                uint32_t r0, r1, r2, r3, s0, s1, s2, s3;
                ldsm4(r0, r1, r2, r3,
                      kBase + ((uint32_t)(buf*32 + ldrow) * 72 + kc*16 + ldcol) * 2u);
                ldsm4(s0, s1, s2, s3,
                      kBase + ((uint32_t)(buf*32 + 16 + ldrow) * 72 + kc*16 + ldcol) * 2u);
                mma_f16(sacc[0][0], sacc[0][1], sacc[0][2], sacc[0][3], a0,a1,a2,a3, r0, r2);
                mma_f16(sacc[1][0], sacc[1][1], sacc[1][2], sacc[1][3], a0,a1,a2,a3, r1, r3);
                mma_f16(sacc[2][0], sacc[2][1], sacc[2][2], sacc[2][3], a0,a1,a2,a3, s0, s2);
                mma_f16(sacc[3][0], sacc[3][1], sacc[3][2], sacc[3][3], a0,a1,a2,a3, s1, s3);
            }

            const bool maskneed = (j0 + 31 > wr);
            #pragma unroll
            for (int rh = 0; rh < 2; ++rh) {
                const int row = wr + gid + rh*8;
                float tmax = -1e30f;
                #pragma unroll
                for (int u = 0; u < 4; ++u) {
                    float x0 = sacc[u][rh*2    ] * 0.03125f;
                    float x1 = sacc[u][rh*2 + 1] * 0.03125f;
                    if (maskneed) {
                        const int c = j0 + u*8 + tig*2;
                        if (c     > row) x0 = -1e30f;
                        if (c + 1 > row) x1 = -1e30f;
                    }
                    sacc[u][rh*2    ] = x0;
                    sacc[u][rh*2 + 1] = x1;
                    tmax = fmaxf(tmax, fmaxf(x0, x1));
                }
                tmax = fmaxf(tmax, __shfl_xor_sync(0xffffffffu, tmax, 1));
                tmax = fmaxf(tmax, __shfl_xor_sync(0xffffffffu, tmax, 2));
                const float mnew = fmaxf(mrow[rh], tmax);
                const float corr = __expf(mrow[rh] - mnew);
                float rsum = 0.f;
                #pragma unroll
                for (int u = 0; u < 4; ++u) {
                    float p0 = __expf(sacc[u][rh*2    ] - mnew);
                    float p1 = __expf(sacc[u][rh*2 + 1] - mnew);
                    rsum += p0 + p1;
                    *(uint32_t*)(&Ph[warp*16 + gid + rh*8][u*8 + tig*2]) = pk16(p0, p1);
                }
                #pragma unroll
                for (int uu = 0; uu < 8; ++uu) {
                    oacc[uu][rh*2    ] *= corr;
                    oacc[uu][rh*2 + 1] *= corr;
                }
                rsum += __shfl_xor_sync(0xffffffffu, rsum, 1);
                rsum += __shfl_xor_sync(0xffffffffu, rsum, 2);
                lrow[rh] = lrow[rh] * corr + rsum;
                mrow[rh] = mnew;
            }
            __syncwarp();

            #pragma unroll
            for (int kc = 0; kc < 2; ++kc) {
                uint32_t a0, a1, a2, a3;
                ldsm4(a0, a1, a2, a3,
                      pBase + ((uint32_t)(warp*16 + ldrow) * 40 + kc*16 + ldcol) * 2u);
                #pragma unroll
                for (int nq = 0; nq < 4; ++nq) {
                    uint32_t r0, r1, r2, r3;
                    ldsm4t(r0, r1, r2, r3,
                           vBase + ((uint32_t)(buf*32 + kc*16 + ldrow) * 72 + nq*16 + ldcol) * 2u);
                    mma_f16(oacc[nq*2  ][0], oacc[nq*2  ][1], oacc[nq*2  ][2], oacc[nq*2  ][3],
                            a0, a1, a2, a3, r0, r1);
                    mma_f16(oacc[nq*2+1][0], oacc[nq*2+1][1], oacc[nq*2+1][2], oacc[nq*2+1][3],
                            a0, a1, a2, a3, r2, r3);
                }
            }
        }
        __syncthreads();
    }
#undef LOAD_KV

    #pragma unroll
    for (int rh = 0; rh < 2; ++rh) {
        const int t = wr + gid + rh*8;
        const float inv = 1.0f / lrow[rh];
        #pragma unroll
        for (int u = 0; u < 8; ++u) {
            const int d = h * HS_ + u*8 + tig*2;
            const size_t o = ((size_t)(b*T_ + t))*D_ + d;
            const float2 e = *(const float2*)(embds + o);
            *(float2*)(out + o) = make_float2(e.x + oacc[u][rh*2    ]*inv,
                                              e.y + oacc[u][rh*2 + 1]*inv);
        }
    }
}

// ---------------- Launcher ----------------
extern "C" void kernel_launch(void* const* d_in, const int* in_sizes, int n_in,
                              void* d_out, int out_size)
{
    const float* embds = (const float*)d_in[0];
    const float* Wq    = (const float*)d_in[1];
    const float* Wk    = (const float*)d_in[2];
    const float* Wv    = (const float*)d_in[3];
    const float* ln1g  = (const float*)d_in[4];
    const float* ln1b  = (const float*)d_in[5];
    const float* ln2g  = (const float*)d_in[6];
    const float* ln2b  = (const float*)d_in[7];
    const float* W1    = (const float*)d_in[8];
    const float* b1    = (const float*)d_in[9];
    const float* W2    = (const float*)d_in[10];
    const float* b2    = (const float*)d_in[11];
    float* out = (float*)d_out;

    __half *xh, *fh, *qh, *kh, *vh;
    float *res1;
    cudaGetSymbolAddress((void**)&xh,   g_xh);
    cudaGetSymbolAddress((void**)&fh,   g_fh);
    cudaGetSymbolAddress((void**)&qh,   g_qh);
    cudaGetSymbolAddress((void**)&kh,   g_kh);
    cudaGetSymbolAddress((void**)&vh,   g_vh);
    cudaGetSymbolAddress((void**)&res1, g_res1);

    // 1. LN1 -> fp16
    ln_kernel<<<BT_, 256>>>(embds, ln1g, ln1b, xh);

    // 2. Fused QKV via gridDim.z -> qh, kh, vh [B,T,H,HS] fp16
    tgemm_kernel<0,128><<<dim3(D_/128, BT_/128, 3), 256>>>(
        xh, Wq, Wk, Wv, nullptr, nullptr, qh, kh, vh, BT_, D_, D_);

    // 3. Flash attention + head-concat + residual -> res1
    flash_kernel<<<dim3(T_/64, BH_), 128>>>(embds, res1);

    // 4. LN2 -> fp16
    ln_kernel<<<BT_, 256>>>(res1, ln2g, ln2b, xh);

    // 5. FFN1: relu(y @ W1 + b1) -> fp16 fh
    tgemm_kernel<1,128><<<dim3(4*D_/128, BT_/128), 256>>>(
        xh, W1, nullptr, nullptr, b1, nullptr, fh, nullptr, nullptr, BT_, 4*D_, D_);

    // 6. FFN2: fh @ W2 + b2 + res1 -> out (fp32), 64-row tiles for wave balance
    tgemm_kernel<2,64><<<dim3(D_/128, BT_/64), 256>>>(
        fh, W2, nullptr, nullptr, b2, res1, out, nullptr, nullptr, BT_, D_, 4*D_);
}